// round 2
// baseline (speedup 1.0000x reference)
#include <cuda_runtime.h>
#include <cuda_bf16.h>
#include <math.h>

// Problem constants
#define BSZ 4
#define TLEN 2048
#define DM 1024
#define DI 2048
#define DS 16
#define DC 4
#define MROWS (BSZ * TLEN)        // 8192
#define NC 64                      // scan chunks
#define CL 32                      // chunk length (NC*CL = TLEN)

// -------- scratch (device globals; allocation-free per harness rules) --------
__device__ float g_xz[(size_t)MROWS * 2 * DI];   // [8192, 4096] in_proj output (x_inner | z)
__device__ float g_xconv[(size_t)MROWS * DI];    // [8192, 2048] conv+silu output
__device__ float g_alpha[MROWS];                 // per (b,t) gate
__device__ float g_P[BSZ * NC];                  // per (b,chunk) alpha product
__device__ float g_S[(size_t)BSZ * NC * DI];     // per (b,chunk,d) local scan end (h0=0)
__device__ float g_H0[(size_t)BSZ * NC * DI];    // per (b,chunk,d) chunk start state
__device__ float g_Y[(size_t)MROWS * DI];        // gated output before out_proj

// ---------------------------------------------------------------------------
// FP32 NT GEMM: C[M,N] = A[M,K] * B[N,K]^T. 128x128 tile, BK=8, 8x8/thread.
// M,N multiples of 128; K multiple of 8 (true for all call sites).
// ---------------------------------------------------------------------------
__global__ __launch_bounds__(256) void sgemm_nt(
    const float* __restrict__ A, const float* __restrict__ Bw,
    float* __restrict__ C, int M, int N, int K)
{
    __shared__ __align__(16) float As[8][128];
    __shared__ __align__(16) float Bs[8][128];
    const int tid = threadIdx.x;
    const int bm = blockIdx.y, bn = blockIdx.x;
    const float* Ab = A + (size_t)bm * 128 * K;
    const float* Bb = Bw + (size_t)bn * 128 * K;
    const int lrow = tid >> 1;            // 0..127
    const int lcol = (tid & 1) << 2;      // 0 or 4
    const int tx = tid & 15, ty = tid >> 4;

    float acc[8][8];
#pragma unroll
    for (int i = 0; i < 8; i++)
#pragma unroll
        for (int j = 0; j < 8; j++) acc[i][j] = 0.f;

    for (int k0 = 0; k0 < K; k0 += 8) {
        float4 a4 = *(const float4*)(Ab + (size_t)lrow * K + k0 + lcol);
        float4 b4 = *(const float4*)(Bb + (size_t)lrow * K + k0 + lcol);
        __syncthreads();
        As[lcol + 0][lrow] = a4.x; As[lcol + 1][lrow] = a4.y;
        As[lcol + 2][lrow] = a4.z; As[lcol + 3][lrow] = a4.w;
        Bs[lcol + 0][lrow] = b4.x; Bs[lcol + 1][lrow] = b4.y;
        Bs[lcol + 2][lrow] = b4.z; Bs[lcol + 3][lrow] = b4.w;
        __syncthreads();
#pragma unroll
        for (int k = 0; k < 8; k++) {
            float af[8], bf[8];
            *(float4*)&af[0] = *(const float4*)&As[k][ty * 8];
            *(float4*)&af[4] = *(const float4*)&As[k][ty * 8 + 4];
            *(float4*)&bf[0] = *(const float4*)&Bs[k][tx * 8];
            *(float4*)&bf[4] = *(const float4*)&Bs[k][tx * 8 + 4];
#pragma unroll
            for (int i = 0; i < 8; i++)
#pragma unroll
                for (int j = 0; j < 8; j++)
                    acc[i][j] = fmaf(af[i], bf[j], acc[i][j]);
        }
    }
#pragma unroll
    for (int i = 0; i < 8; i++) {
        size_t row = (size_t)bm * 128 + ty * 8 + i;
        float* Cp = C + row * N + bn * 128 + tx * 8;
        *(float4*)Cp       = make_float4(acc[i][0], acc[i][1], acc[i][2], acc[i][3]);
        *(float4*)(Cp + 4) = make_float4(acc[i][4], acc[i][5], acc[i][6], acc[i][7]);
    }
}

__device__ __forceinline__ float sigmoidf_(float v) { return 1.f / (1.f + expf(-v)); }
__device__ __forceinline__ float siluf_(float v)    { return v * sigmoidf_(v); }

// ---------------------------------------------------------------------------
// Depthwise causal conv (k=4) + SiLU. x_inner = g_xz[:, 0:DI].
// Grid: (DI/256, TLEN/32, BSZ), 256 threads (one d per thread).
// ---------------------------------------------------------------------------
__global__ __launch_bounds__(256) void conv_silu_kernel(
    const float* __restrict__ cw, const float* __restrict__ cb)
{
    const int d  = blockIdx.x * 256 + threadIdx.x;
    const int b  = blockIdx.z;
    const int t0 = blockIdx.y * 32;
    const float* xin = g_xz + (size_t)b * TLEN * (2 * DI) + d;   // stride 2*DI per t
    float* xco = g_xconv + ((size_t)b * TLEN + t0) * DI + d;

    const float w0 = cw[d * 4 + 0], w1 = cw[d * 4 + 1];
    const float w2 = cw[d * 4 + 2], w3 = cw[d * 4 + 3];
    const float bias = cb[d];

    float xm3 = (t0 - 3 >= 0) ? xin[(size_t)(t0 - 3) * (2 * DI)] : 0.f;
    float xm2 = (t0 - 2 >= 0) ? xin[(size_t)(t0 - 2) * (2 * DI)] : 0.f;
    float xm1 = (t0 - 1 >= 0) ? xin[(size_t)(t0 - 1) * (2 * DI)] : 0.f;
#pragma unroll 4
    for (int tt = 0; tt < 32; tt++) {
        float xc = xin[(size_t)(t0 + tt) * (2 * DI)];
        float v = w0 * xm3 + w1 * xm2 + w2 * xm1 + w3 * xc + bias;
        xco[(size_t)tt * DI] = siluf_(v);
        xm3 = xm2; xm2 = xm1; xm1 = xc;
    }
}

// ---------------------------------------------------------------------------
// Per-row (b,t): B_ssm[16] = x_conv . x_proj_w[0:16]^T, then
// alpha = sigmoid(mean_d softplus(B_ssm . dt_w[d] + dt_b[d])).
// Grid: MROWS blocks, 256 threads.
// ---------------------------------------------------------------------------
__global__ __launch_bounds__(256) void alpha_kernel(
    const float* __restrict__ xpw, const float* __restrict__ dtw,
    const float* __restrict__ dtb)
{
    const int row = blockIdx.x;
    const int tid = threadIdx.x;
    const float* xc = g_xconv + (size_t)row * DI;

    __shared__ float bsm[DS];
    __shared__ float red[8];
    if (tid < DS) bsm[tid] = 0.f;
    __syncthreads();

    float part[DS];
#pragma unroll
    for (int n = 0; n < DS; n++) part[n] = 0.f;
    for (int d = tid; d < DI; d += 256) {
        float xv = xc[d];
#pragma unroll
        for (int n = 0; n < DS; n++) part[n] = fmaf(xv, xpw[n * DI + d], part[n]);
    }
#pragma unroll
    for (int n = 0; n < DS; n++) {
#pragma unroll
        for (int o = 16; o; o >>= 1) part[n] += __shfl_xor_sync(0xffffffffu, part[n], o);
    }
    if ((tid & 31) == 0) {
#pragma unroll
        for (int n = 0; n < DS; n++) atomicAdd(&bsm[n], part[n]);
    }
    __syncthreads();

    float lsum = 0.f;
    for (int d = tid; d < DI; d += 256) {
        float s = dtb[d];
#pragma unroll
        for (int n = 0; n < DS; n++) s = fmaf(bsm[n], dtw[d * DS + n], s);
        float sp = (s > 20.f) ? s : log1pf(expf(s));   // softplus
        lsum += sp;
    }
#pragma unroll
    for (int o = 16; o; o >>= 1) lsum += __shfl_xor_sync(0xffffffffu, lsum, o);
    if ((tid & 31) == 0) red[tid >> 5] = lsum;
    __syncthreads();
    if (tid == 0) {
        float s = 0.f;
#pragma unroll
        for (int i = 0; i < 8; i++) s += red[i];
        g_alpha[row] = sigmoidf_(s / (float)DI);
    }
}

// Per (b,chunk) alpha product. One block, 256 threads = BSZ*NC lanes.
__global__ void chunkP_kernel()
{
    const int id = threadIdx.x;        // BSZ*NC = 256
    const int b = id / NC, c = id % NC;
    const float* al = g_alpha + b * TLEN + c * CL;
    float p = 1.f;
#pragma unroll
    for (int tt = 0; tt < CL; tt++) p *= al[tt];
    g_P[id] = p;
}

// Pass 1: local scan ends with h0=0.  Grid: (DI/256, NC, BSZ)
__global__ __launch_bounds__(256) void scan1_kernel()
{
    const int d = blockIdx.x * 256 + threadIdx.x;
    const int c = blockIdx.y, b = blockIdx.z;
    const float* xc = g_xconv + ((size_t)b * TLEN + c * CL) * DI + d;
    const float* al = g_alpha + b * TLEN + c * CL;
    float h = 0.f;
#pragma unroll 8
    for (int tt = 0; tt < CL; tt++) {
        float a = al[tt];
        h = fmaf(a, h, (1.f - a) * xc[(size_t)tt * DI]);
    }
    g_S[((size_t)(b * NC + c)) * DI + d] = h;
}

// Pass 2: cross-chunk recurrence. 32 blocks x 256 = 8192 lanes (b,d).
__global__ __launch_bounds__(256) void scan2_kernel()
{
    const int id = blockIdx.x * 256 + threadIdx.x;
    const int b = id / DI, d = id % DI;
    float h = 0.f;
    g_H0[((size_t)(b * NC + 0)) * DI + d] = 0.f;
#pragma unroll 4
    for (int c = 0; c < NC - 1; c++) {
        h = fmaf(g_P[b * NC + c], h, g_S[((size_t)(b * NC + c)) * DI + d]);
        g_H0[((size_t)(b * NC + c + 1)) * DI + d] = h;
    }
}

// Pass 3: seeded replay + D-skip + SiLU(z) gate.  Grid: (DI/256, NC, BSZ)
__global__ __launch_bounds__(256) void scan3_kernel(const float* __restrict__ Dp)
{
    const int d = blockIdx.x * 256 + threadIdx.x;
    const int c = blockIdx.y, b = blockIdx.z;
    const size_t rbase = (size_t)b * TLEN + c * CL;
    const float* xc = g_xconv + rbase * DI + d;
    const float* zp = g_xz + rbase * (2 * DI) + DI + d;
    const float* al = g_alpha + b * TLEN + c * CL;
    float* yo = g_Y + rbase * DI + d;
    const float Dv = Dp[d];
    float h = g_H0[((size_t)(b * NC + c)) * DI + d];
#pragma unroll 4
    for (int tt = 0; tt < CL; tt++) {
        float a = al[tt];
        float x = xc[(size_t)tt * DI];
        h = fmaf(a, h, (1.f - a) * x);
        float y = fmaf(h, Dv, x);
        float z = zp[(size_t)tt * (2 * DI)];
        yo[(size_t)tt * DI] = y * siluf_(z);
    }
}

// ---------------------------------------------------------------------------
extern "C" void kernel_launch(void* const* d_in, const int* in_sizes, int n_in,
                              void* d_out, int out_size)
{
    const float* x    = (const float*)d_in[0];   // [B,T,DM]
    const float* win  = (const float*)d_in[1];   // [2*DI, DM]
    const float* cw   = (const float*)d_in[2];   // [DI,1,DC]
    const float* cb   = (const float*)d_in[3];   // [DI]
    const float* xpw  = (const float*)d_in[4];   // [2*DS, DI]
    const float* dtw  = (const float*)d_in[5];   // [DI, DS]
    const float* dtb  = (const float*)d_in[6];   // [DI]
    const float* Dp   = (const float*)d_in[7];   // [DI]
    const float* wout = (const float*)d_in[8];   // [DM, DI]
    float* out = (float*)d_out;                  // [B,T,DM]

    float* xz;  cudaGetSymbolAddress((void**)&xz, g_xz);
    float* Y;   cudaGetSymbolAddress((void**)&Y,  g_Y);

    // 1) in_proj: [8192,1024] x [4096,1024]^T -> [8192,4096]
    sgemm_nt<<<dim3((2 * DI) / 128, MROWS / 128), 256>>>(x, win, xz, MROWS, 2 * DI, DM);
    // 2) depthwise causal conv + SiLU
    conv_silu_kernel<<<dim3(DI / 256, TLEN / 32, BSZ), 256>>>(cw, cb);
    // 3) B_ssm + dt + alpha per row
    alpha_kernel<<<MROWS, 256>>>(xpw, dtw, dtb);
    // 4) chunked scan
    chunkP_kernel<<<1, BSZ * NC>>>();
    scan1_kernel<<<dim3(DI / 256, NC, BSZ), 256>>>();
    scan2_kernel<<<MROWS / 256, 256>>>();
    scan3_kernel<<<dim3(DI / 256, NC, BSZ), 256>>>(Dp);
    // 5) out_proj: [8192,2048] x [1024,2048]^T -> [8192,1024]
    sgemm_nt<<<dim3(DM / 128, MROWS / 128), 256>>>(Y, wout, out, MROWS, DM, DI);
}

// round 4
// speedup vs baseline: 1.5422x; 1.5422x over previous
#include <cuda_runtime.h>
#include <cuda_bf16.h>
#include <math.h>
#include <stdint.h>

// Problem constants
#define BSZ 4
#define TLEN 2048
#define DM 1024
#define DI 2048
#define DS 16
#define DC 4
#define MROWS (BSZ * TLEN)        // 8192
#define NC 64                      // scan chunks
#define CL 32                      // chunk length (NC*CL = TLEN)

// -------- scratch (device globals; allocation-free per harness rules) --------
__device__ float g_xz[(size_t)MROWS * 2 * DI];   // [8192, 4096] in_proj out (x_inner | z)
__device__ float g_xconv[(size_t)MROWS * DI];    // [8192, 2048] conv+silu output
__device__ float g_alpha[MROWS];                 // per (b,t) gate
__device__ float g_P[BSZ * NC];                  // per (b,chunk) alpha product
__device__ float g_S[(size_t)BSZ * NC * DI];     // local scan end (h0=0)
__device__ float g_H0[(size_t)BSZ * NC * DI];    // chunk start state
__device__ float g_Y[(size_t)MROWS * DI];        // gated output before out_proj

// ============================ helpers =======================================
__device__ __forceinline__ uint32_t smem_u32(const void* p) {
    uint32_t a;
    asm("{ .reg .u64 t; cvta.to.shared.u64 t, %1; cvt.u32.u64 %0, t; }"
        : "=r"(a) : "l"(p));
    return a;
}

__device__ __forceinline__ void ldx4(uint32_t* r, uint32_t addr) {
    asm volatile("ldmatrix.sync.aligned.m8n8.x4.shared.b16 {%0,%1,%2,%3}, [%4];"
        : "=r"(r[0]), "=r"(r[1]), "=r"(r[2]), "=r"(r[3]) : "r"(addr));
}

__device__ __forceinline__ void mma16816(float* c, const uint32_t* a,
                                         uint32_t b0, uint32_t b1) {
    asm volatile(
        "mma.sync.aligned.m16n8k16.row.col.f32.bf16.bf16.f32 "
        "{%0,%1,%2,%3}, {%4,%5,%6,%7}, {%8,%9}, {%0,%1,%2,%3};"
        : "+f"(c[0]), "+f"(c[1]), "+f"(c[2]), "+f"(c[3])
        : "r"(a[0]), "r"(a[1]), "r"(a[2]), "r"(a[3]), "r"(b0), "r"(b1));
}

// Convert 16 fp32 -> 16 bf16 hi (2 x uint4) + 16 bf16 lo (2 x uint4).
// v = hi + lo exactly up to O(2^-18 |v|).
__device__ __forceinline__ void cvt16(const float* v, uint4* hi, uint4* lo) {
    uint32_t* hp = (uint32_t*)hi;
    uint32_t* lp = (uint32_t*)lo;
#pragma unroll
    for (int i = 0; i < 8; i++) {
        float h0 = __bfloat162float(__float2bfloat16_rn(v[2 * i]));
        float h1 = __bfloat162float(__float2bfloat16_rn(v[2 * i + 1]));
        __nv_bfloat162 h2 = __floats2bfloat162_rn(h0, h1);
        __nv_bfloat162 l2 = __floats2bfloat162_rn(v[2 * i] - h0, v[2 * i + 1] - h1);
        hp[i] = *(uint32_t*)&h2;
        lp[i] = *(uint32_t*)&l2;
    }
}

// ---------------------------------------------------------------------------
// Split-bf16 NT GEMM via mma.sync: C[M,N] = A[M,K] * B[N,K]^T (fp32 in/out).
// CTA 128x128, 8 warps (2x4), warp tile 64x32. K-chunk 32 fp32 -> bf16 hi/lo
// in SMEM (80B padded rows, ldmatrix conflict-free). 3 split terms, fp32 acc.
// ---------------------------------------------------------------------------
#define KC    32                   // k per chunk
#define ROWB  80                   // padded bytes per smem row (32 bf16 = 64B + 16)
#define TILEB (128 * ROWB)         // 10240 bytes per tile
#define STGB  (4 * TILEB)          // Ah, Al, Bh, Bl
#define GSMEM (2 * STGB)           // 81920 double-buffered

__global__ __launch_bounds__(256) void gemm3_mma(
    const float* __restrict__ A, const float* __restrict__ Bw,
    float* __restrict__ C, int N, int K)
{
    extern __shared__ char smem[];
    const uint32_t sb = smem_u32(smem);
    const int tid = threadIdx.x, lane = tid & 31, wid = tid >> 5;
    const int bm = blockIdx.y, bn = blockIdx.x;
    const int warp_m = wid >> 2, warp_n = wid & 3;   // 2 x 4 warps

    const int r = tid >> 1, half = tid & 1;          // 128 rows x 2 halves
    const float* Ap = A + (size_t)(bm * 128 + r) * K + half * 16;
    const float* Bp = Bw + (size_t)(bn * 128 + r) * K + half * 16;
    const uint32_t stoff = (uint32_t)(r * ROWB + half * 32);

    float acc[4][4][4];
#pragma unroll
    for (int i = 0; i < 4; i++)
#pragma unroll
        for (int j = 0; j < 4; j++)
#pragma unroll
            for (int q = 0; q < 4; q++) acc[i][j][q] = 0.f;

    // ldmatrix base addresses (per-warp, lane-dependent)
    const uint32_t lrow = lane & 15, lcolb = (lane >> 4) * 16;
    const uint32_t a_lm = (uint32_t)((warp_m * 64 + lrow) * ROWB) + lcolb;
    const uint32_t b_lm = (uint32_t)((warp_n * 32 + lrow) * ROWB) + lcolb;

    float va[16], vb[16];
    // prefetch chunk 0
#pragma unroll
    for (int j = 0; j < 4; j++) {
        *(float4*)&va[j * 4] = *(const float4*)(Ap + j * 4);
        *(float4*)&vb[j * 4] = *(const float4*)(Bp + j * 4);
    }
    {   // store chunk 0 -> stage 0
        uint4 h[2], l[2];
        cvt16(va, h, l);
        *(uint4*)(smem + 0 * TILEB + stoff) = h[0];
        *(uint4*)(smem + 0 * TILEB + stoff + 16) = h[1];
        *(uint4*)(smem + 1 * TILEB + stoff) = l[0];
        *(uint4*)(smem + 1 * TILEB + stoff + 16) = l[1];
        cvt16(vb, h, l);
        *(uint4*)(smem + 2 * TILEB + stoff) = h[0];
        *(uint4*)(smem + 2 * TILEB + stoff + 16) = h[1];
        *(uint4*)(smem + 3 * TILEB + stoff) = l[0];
        *(uint4*)(smem + 3 * TILEB + stoff + 16) = l[1];
    }
    __syncthreads();

    const int nch = K / KC;
    for (int ch = 0; ch < nch; ch++) {
        // prefetch next chunk into registers (overlaps with MMA below)
        if (ch + 1 < nch) {
            const float* Ac = Ap + (size_t)(ch + 1) * KC;
            const float* Bc = Bp + (size_t)(ch + 1) * KC;
#pragma unroll
            for (int j = 0; j < 4; j++) {
                *(float4*)&va[j * 4] = *(const float4*)(Ac + j * 4);
                *(float4*)&vb[j * 4] = *(const float4*)(Bc + j * 4);
            }
        }
        // compute on stage ch&1
        const uint32_t st = sb + (uint32_t)(ch & 1) * STGB;
#pragma unroll
        for (int ks = 0; ks < 2; ks++) {
            uint32_t Ah[4][4], Al[4][4], Bh[4][2], Bl[4][2];
#pragma unroll
            for (int ma = 0; ma < 4; ma++) {
                uint32_t ad = st + a_lm + (uint32_t)(ma * 16 * ROWB) + ks * 32;
                ldx4(Ah[ma], ad);
                ldx4(Al[ma], ad + TILEB);
            }
#pragma unroll
            for (int p = 0; p < 2; p++) {
                uint32_t bd = st + 2 * TILEB + b_lm + (uint32_t)(p * 16 * ROWB) + ks * 32;
                uint32_t q[4];
                ldx4(q, bd);
                Bh[2 * p][0] = q[0]; Bh[2 * p][1] = q[2];
                Bh[2 * p + 1][0] = q[1]; Bh[2 * p + 1][1] = q[3];
                ldx4(q, bd + TILEB);
                Bl[2 * p][0] = q[0]; Bl[2 * p][1] = q[2];
                Bl[2 * p + 1][0] = q[1]; Bl[2 * p + 1][1] = q[3];
            }
#pragma unroll
            for (int ma = 0; ma < 4; ma++)
#pragma unroll
                for (int na = 0; na < 4; na++) {
                    mma16816(acc[ma][na], Ah[ma], Bh[na][0], Bh[na][1]);
                    mma16816(acc[ma][na], Al[ma], Bh[na][0], Bh[na][1]);
                    mma16816(acc[ma][na], Ah[ma], Bl[na][0], Bl[na][1]);
                }
        }
        __syncthreads();
        if (ch + 1 < nch) {
            char* dst = smem + ((ch + 1) & 1) * STGB;
            uint4 h[2], l[2];
            cvt16(va, h, l);
            *(uint4*)(dst + 0 * TILEB + stoff) = h[0];
            *(uint4*)(dst + 0 * TILEB + stoff + 16) = h[1];
            *(uint4*)(dst + 1 * TILEB + stoff) = l[0];
            *(uint4*)(dst + 1 * TILEB + stoff + 16) = l[1];
            cvt16(vb, h, l);
            *(uint4*)(dst + 2 * TILEB + stoff) = h[0];
            *(uint4*)(dst + 2 * TILEB + stoff + 16) = h[1];
            *(uint4*)(dst + 3 * TILEB + stoff) = l[0];
            *(uint4*)(dst + 3 * TILEB + stoff + 16) = l[1];
            __syncthreads();
        }
    }

    // epilogue: direct fp32 stores
    const int row_b = bm * 128 + warp_m * 64 + (lane >> 2);
    const int col_b = bn * 128 + warp_n * 32 + ((lane & 3) << 1);
#pragma unroll
    for (int ma = 0; ma < 4; ma++) {
#pragma unroll
        for (int na = 0; na < 4; na++) {
            float* c0 = C + (size_t)(row_b + ma * 16) * N + col_b + na * 8;
            float* c1 = c0 + (size_t)8 * N;
            *(float2*)c0 = make_float2(acc[ma][na][0], acc[ma][na][1]);
            *(float2*)c1 = make_float2(acc[ma][na][2], acc[ma][na][3]);
        }
    }
}

// ============================ elementwise / scan =============================
__device__ __forceinline__ float sigmoidf_(float v) { return 1.f / (1.f + expf(-v)); }
__device__ __forceinline__ float siluf_(float v)    { return v * sigmoidf_(v); }

__global__ __launch_bounds__(256) void conv_silu_kernel(
    const float* __restrict__ cw, const float* __restrict__ cb)
{
    const int d  = blockIdx.x * 256 + threadIdx.x;
    const int b  = blockIdx.z;
    const int t0 = blockIdx.y * 32;
    const float* xin = g_xz + (size_t)b * TLEN * (2 * DI) + d;
    float* xco = g_xconv + ((size_t)b * TLEN + t0) * DI + d;

    const float w0 = cw[d * 4 + 0], w1 = cw[d * 4 + 1];
    const float w2 = cw[d * 4 + 2], w3 = cw[d * 4 + 3];
    const float bias = cb[d];

    float xm3 = (t0 - 3 >= 0) ? xin[(size_t)(t0 - 3) * (2 * DI)] : 0.f;
    float xm2 = (t0 - 2 >= 0) ? xin[(size_t)(t0 - 2) * (2 * DI)] : 0.f;
    float xm1 = (t0 - 1 >= 0) ? xin[(size_t)(t0 - 1) * (2 * DI)] : 0.f;
#pragma unroll 4
    for (int tt = 0; tt < 32; tt++) {
        float xc = xin[(size_t)(t0 + tt) * (2 * DI)];
        float v = w0 * xm3 + w1 * xm2 + w2 * xm1 + w3 * xc + bias;
        xco[(size_t)tt * DI] = siluf_(v);
        xm3 = xm2; xm2 = xm1; xm1 = xc;
    }
}

__global__ __launch_bounds__(256) void alpha_kernel(
    const float* __restrict__ xpw, const float* __restrict__ dtw,
    const float* __restrict__ dtb)
{
    const int row = blockIdx.x;
    const int tid = threadIdx.x;
    const float* xc = g_xconv + (size_t)row * DI;

    __shared__ float bsm[DS];
    __shared__ float red[8];
    if (tid < DS) bsm[tid] = 0.f;
    __syncthreads();

    float part[DS];
#pragma unroll
    for (int n = 0; n < DS; n++) part[n] = 0.f;
    for (int d = tid; d < DI; d += 256) {
        float xv = xc[d];
#pragma unroll
        for (int n = 0; n < DS; n++) part[n] = fmaf(xv, xpw[n * DI + d], part[n]);
    }
#pragma unroll
    for (int n = 0; n < DS; n++) {
#pragma unroll
        for (int o = 16; o; o >>= 1) part[n] += __shfl_xor_sync(0xffffffffu, part[n], o);
    }
    if ((tid & 31) == 0) {
#pragma unroll
        for (int n = 0; n < DS; n++) atomicAdd(&bsm[n], part[n]);
    }
    __syncthreads();

    float lsum = 0.f;
    for (int d = tid; d < DI; d += 256) {
        float s = dtb[d];
#pragma unroll
        for (int n = 0; n < DS; n++) s = fmaf(bsm[n], dtw[d * DS + n], s);
        float sp = (s > 20.f) ? s : log1pf(expf(s));
        lsum += sp;
    }
#pragma unroll
    for (int o = 16; o; o >>= 1) lsum += __shfl_xor_sync(0xffffffffu, lsum, o);
    if ((tid & 31) == 0) red[tid >> 5] = lsum;
    __syncthreads();
    if (tid == 0) {
        float s = 0.f;
#pragma unroll
        for (int i = 0; i < 8; i++) s += red[i];
        g_alpha[row] = sigmoidf_(s / (float)DI);
    }
}

__global__ void chunkP_kernel()
{
    const int id = threadIdx.x;
    const int b = id / NC, c = id % NC;
    const float* al = g_alpha + b * TLEN + c * CL;
    float p = 1.f;
#pragma unroll
    for (int tt = 0; tt < CL; tt++) p *= al[tt];
    g_P[id] = p;
}

__global__ __launch_bounds__(256) void scan1_kernel()
{
    const int d = blockIdx.x * 256 + threadIdx.x;
    const int c = blockIdx.y, b = blockIdx.z;
    const float* xc = g_xconv + ((size_t)b * TLEN + c * CL) * DI + d;
    const float* al = g_alpha + b * TLEN + c * CL;
    float h = 0.f;
#pragma unroll 8
    for (int tt = 0; tt < CL; tt++) {
        float a = al[tt];
        h = fmaf(a, h, (1.f - a) * xc[(size_t)tt * DI]);
    }
    g_S[((size_t)(b * NC + c)) * DI + d] = h;
}

__global__ __launch_bounds__(256) void scan2_kernel()
{
    const int id = blockIdx.x * 256 + threadIdx.x;
    const int b = id / DI, d = id % DI;
    float h = 0.f;
    g_H0[((size_t)(b * NC + 0)) * DI + d] = 0.f;
#pragma unroll 4
    for (int c = 0; c < NC - 1; c++) {
        h = fmaf(g_P[b * NC + c], h, g_S[((size_t)(b * NC + c)) * DI + d]);
        g_H0[((size_t)(b * NC + c + 1)) * DI + d] = h;
    }
}

__global__ __launch_bounds__(256) void scan3_kernel(const float* __restrict__ Dp)
{
    const int d = blockIdx.x * 256 + threadIdx.x;
    const int c = blockIdx.y, b = blockIdx.z;
    const size_t rbase = (size_t)b * TLEN + c * CL;
    const float* xc = g_xconv + rbase * DI + d;
    const float* zp = g_xz + rbase * (2 * DI) + DI + d;
    const float* al = g_alpha + b * TLEN + c * CL;
    float* yo = g_Y + rbase * DI + d;
    const float Dv = Dp[d];
    float h = g_H0[((size_t)(b * NC + c)) * DI + d];
#pragma unroll 4
    for (int tt = 0; tt < CL; tt++) {
        float a = al[tt];
        float x = xc[(size_t)tt * DI];
        h = fmaf(a, h, (1.f - a) * x);
        float y = fmaf(h, Dv, x);
        float z = zp[(size_t)tt * (2 * DI)];
        yo[(size_t)tt * DI] = y * siluf_(z);
    }
}

// ---------------------------------------------------------------------------
extern "C" void kernel_launch(void* const* d_in, const int* in_sizes, int n_in,
                              void* d_out, int out_size)
{
    const float* x    = (const float*)d_in[0];   // [B,T,DM]
    const float* win  = (const float*)d_in[1];   // [2*DI, DM]
    const float* cw   = (const float*)d_in[2];   // [DI,1,DC]
    const float* cb   = (const float*)d_in[3];   // [DI]
    const float* xpw  = (const float*)d_in[4];   // [2*DS, DI]
    const float* dtw  = (const float*)d_in[5];   // [DI, DS]
    const float* dtb  = (const float*)d_in[6];   // [DI]
    const float* Dp   = (const float*)d_in[7];   // [DI]
    const float* wout = (const float*)d_in[8];   // [DM, DI]
    float* out = (float*)d_out;                  // [B,T,DM]

    float* xz;  cudaGetSymbolAddress((void**)&xz, g_xz);
    float* Y;   cudaGetSymbolAddress((void**)&Y,  g_Y);

    cudaFuncSetAttribute(gemm3_mma, cudaFuncAttributeMaxDynamicSharedMemorySize,
                         GSMEM);

    // 1) in_proj: [8192,1024] x [4096,1024]^T -> [8192,4096]  (split-bf16 mma.sync)
    gemm3_mma<<<dim3((2 * DI) / 128, MROWS / 128), 256, GSMEM>>>(
        x, win, xz, 2 * DI, DM);
    // 2) depthwise causal conv + SiLU
    conv_silu_kernel<<<dim3(DI / 256, TLEN / 32, BSZ), 256>>>(cw, cb);
    // 3) B_ssm + dt + alpha per row
    alpha_kernel<<<MROWS, 256>>>(xpw, dtw, dtb);
    // 4) chunked scan
    chunkP_kernel<<<1, BSZ * NC>>>();
    scan1_kernel<<<dim3(DI / 256, NC, BSZ), 256>>>();
    scan2_kernel<<<MROWS / 256, 256>>>();
    scan3_kernel<<<dim3(DI / 256, NC, BSZ), 256>>>(Dp);
    // 5) out_proj: [8192,2048] x [1024,2048]^T -> [8192,1024]  (split-bf16 mma.sync)
    gemm3_mma<<<dim3(DM / 128, MROWS / 128), 256, GSMEM>>>(
        Y, wout, out, DM, DI);
}

// round 5
// speedup vs baseline: 1.8563x; 1.2037x over previous
#include <cuda_runtime.h>
#include <cuda_bf16.h>
#include <math.h>
#include <stdint.h>

// Problem constants
#define BSZ 4
#define TLEN 2048
#define DM 1024
#define DI 2048
#define DS 16
#define DC 4
#define MROWS (BSZ * TLEN)        // 8192
#define NC 64                      // scan chunks
#define CL 32                      // chunk length (NC*CL = TLEN)

// -------- scratch (device globals; allocation-free per harness rules) --------
__device__ float g_xz[(size_t)MROWS * 2 * DI];   // in_proj out (x_inner | z) fp32
__device__ float g_xconv[(size_t)MROWS * DI];    // conv+silu output
__device__ float g_alpha[MROWS];                 // per (b,t) gate
__device__ float g_S[(size_t)BSZ * NC * DI];     // local scan end (h0=0)
__device__ float g_H0[(size_t)BSZ * NC * DI];    // chunk start state
// split-bf16 operand copies
__device__ __nv_bfloat16 g_xh[(size_t)MROWS * DM],  g_xl[(size_t)MROWS * DM];
__device__ __nv_bfloat16 g_wih[(size_t)2 * DI * DM], g_wil[(size_t)2 * DI * DM];
__device__ __nv_bfloat16 g_yh[(size_t)MROWS * DI],  g_yl[(size_t)MROWS * DI];
__device__ __nv_bfloat16 g_woh[(size_t)DM * DI],    g_wol[(size_t)DM * DI];

// ============================ helpers =======================================
__device__ __forceinline__ uint32_t smem_u32(const void* p) {
    uint32_t a;
    asm("{ .reg .u64 t; cvta.to.shared.u64 t, %1; cvt.u32.u64 %0, t; }"
        : "=r"(a) : "l"(p));
    return a;
}
__device__ __forceinline__ void ldx4(uint32_t* r, uint32_t addr) {
    asm volatile("ldmatrix.sync.aligned.m8n8.x4.shared.b16 {%0,%1,%2,%3}, [%4];"
        : "=r"(r[0]), "=r"(r[1]), "=r"(r[2]), "=r"(r[3]) : "r"(addr));
}
__device__ __forceinline__ void mma16816(float* c, const uint32_t* a,
                                         uint32_t b0, uint32_t b1) {
    asm volatile(
        "mma.sync.aligned.m16n8k16.row.col.f32.bf16.bf16.f32 "
        "{%0,%1,%2,%3}, {%4,%5,%6,%7}, {%8,%9}, {%0,%1,%2,%3};"
        : "+f"(c[0]), "+f"(c[1]), "+f"(c[2]), "+f"(c[3])
        : "r"(a[0]), "r"(a[1]), "r"(a[2]), "r"(a[3]), "r"(b0), "r"(b1));
}
__device__ __forceinline__ void cp16(uint32_t s, const void* g) {
    asm volatile("cp.async.cg.shared.global [%0], [%1], 16;"
        :: "r"(s), "l"(g) : "memory");
}

// ---------------------------------------------------------------------------
// fp32 -> (hi, lo) bf16 split, float4-vectorized. n must be divisible by 4.
// ---------------------------------------------------------------------------
__global__ __launch_bounds__(256) void cvt_split_kernel(
    const float* __restrict__ src, __nv_bfloat16* __restrict__ hi,
    __nv_bfloat16* __restrict__ lo, int n4)
{
    int i = blockIdx.x * 256 + threadIdx.x;
    if (i >= n4) return;
    float4 v = ((const float4*)src)[i];
    float vv[4] = {v.x, v.y, v.z, v.w};
    __nv_bfloat16 h[4], l[4];
#pragma unroll
    for (int k = 0; k < 4; k++) {
        h[k] = __float2bfloat16_rn(vv[k]);
        l[k] = __float2bfloat16_rn(vv[k] - __bfloat162float(h[k]));
    }
    ((uint2*)hi)[i] = *(uint2*)h;
    ((uint2*)lo)[i] = *(uint2*)l;
}

// ---------------------------------------------------------------------------
// Split-bf16 NT GEMM via mma.sync, bf16 hi/lo operands resident in GMEM.
// C[M,N] = (Ah+Al)[M,K] * (Bh+Bl)[N,K]^T  (3-term: AhBh + AlBh + AhBl).
// CTA 128x128, 8 warps (2x4), warp tile 64x32, K-chunk 32, cp.async
// double-buffer (load ch+2 overlaps compute ch+1). fp32 accum + epilogue.
// ---------------------------------------------------------------------------
#define KC    32
#define ROWB  80                   // 64B data + 16B pad (ldmatrix conflict-free)
#define TILEB (128 * ROWB)         // 10240
#define STGB  (4 * TILEB)          // Ah, Al, Bh, Bl = 40960
#define GSMEM (2 * STGB)           // 81920

__global__ __launch_bounds__(256) void gemm3_bf(
    const __nv_bfloat16* __restrict__ Ah_, const __nv_bfloat16* __restrict__ Al_,
    const __nv_bfloat16* __restrict__ Bh_, const __nv_bfloat16* __restrict__ Bl_,
    float* __restrict__ C, int N, int K)
{
    extern __shared__ char smem[];
    const uint32_t sb = smem_u32(smem);
    const int tid = threadIdx.x, lane = tid & 31, wid = tid >> 5;
    const int bm = blockIdx.y, bn = blockIdx.x;
    const int warp_m = wid >> 2, warp_n = wid & 3;

    const int r = tid >> 1, half = tid & 1;
    const size_t arow = (size_t)(bm * 128 + r) * K;
    const size_t brow = (size_t)(bn * 128 + r) * K;
    const uint32_t soff = (uint32_t)(r * ROWB + half * 32);

    float acc[4][4][4];
#pragma unroll
    for (int i = 0; i < 4; i++)
#pragma unroll
        for (int j = 0; j < 4; j++)
#pragma unroll
            for (int q = 0; q < 4; q++) acc[i][j][q] = 0.f;

    const int nch = K / KC;

#define ISSUE(ch) do { \
        uint32_t dst = sb + (uint32_t)((ch) & 1) * STGB + soff; \
        size_t koff = (size_t)(ch) * KC + half * 16; \
        cp16(dst + 0 * TILEB,      Ah_ + arow + koff); \
        cp16(dst + 0 * TILEB + 16, Ah_ + arow + koff + 8); \
        cp16(dst + 1 * TILEB,      Al_ + arow + koff); \
        cp16(dst + 1 * TILEB + 16, Al_ + arow + koff + 8); \
        cp16(dst + 2 * TILEB,      Bh_ + brow + koff); \
        cp16(dst + 2 * TILEB + 16, Bh_ + brow + koff + 8); \
        cp16(dst + 3 * TILEB,      Bl_ + brow + koff); \
        cp16(dst + 3 * TILEB + 16, Bl_ + brow + koff + 8); \
        asm volatile("cp.async.commit_group;" ::: "memory"); \
    } while (0)

    ISSUE(0);
    ISSUE(1);

    // ldmatrix lane addressing
    const uint32_t lrow = lane & 15, lcolb = (lane >> 4) * 16;
    const uint32_t a_lm = (uint32_t)((warp_m * 64 + lrow) * ROWB) + lcolb;
    const uint32_t b_lm = (uint32_t)((warp_n * 32 + lrow) * ROWB) + lcolb;

    for (int ch = 0; ch < nch; ch++) {
        if (ch + 1 < nch)
            asm volatile("cp.async.wait_group 1;" ::: "memory");
        else
            asm volatile("cp.async.wait_group 0;" ::: "memory");
        __syncthreads();

        const uint32_t st = sb + (uint32_t)(ch & 1) * STGB;
#pragma unroll
        for (int ks = 0; ks < 2; ks++) {
            uint32_t Ah[4][4], Al[4][4], Bh[4][2], Bl[4][2];
#pragma unroll
            for (int ma = 0; ma < 4; ma++) {
                uint32_t ad = st + a_lm + (uint32_t)(ma * 16 * ROWB) + ks * 32;
                ldx4(Ah[ma], ad);
                ldx4(Al[ma], ad + TILEB);
            }
#pragma unroll
            for (int p = 0; p < 2; p++) {
                uint32_t bd = st + 2 * TILEB + b_lm + (uint32_t)(p * 16 * ROWB) + ks * 32;
                uint32_t q[4];
                ldx4(q, bd);
                Bh[2 * p][0] = q[0]; Bh[2 * p][1] = q[2];
                Bh[2 * p + 1][0] = q[1]; Bh[2 * p + 1][1] = q[3];
                ldx4(q, bd + TILEB);
                Bl[2 * p][0] = q[0]; Bl[2 * p][1] = q[2];
                Bl[2 * p + 1][0] = q[1]; Bl[2 * p + 1][1] = q[3];
            }
#pragma unroll
            for (int ma = 0; ma < 4; ma++)
#pragma unroll
                for (int na = 0; na < 4; na++) {
                    mma16816(acc[ma][na], Ah[ma], Bh[na][0], Bh[na][1]);
                    mma16816(acc[ma][na], Al[ma], Bh[na][0], Bh[na][1]);
                    mma16816(acc[ma][na], Ah[ma], Bl[na][0], Bl[na][1]);
                }
        }
        __syncthreads();
        if (ch + 2 < nch) ISSUE(ch + 2);
    }
#undef ISSUE

    const int row_b = bm * 128 + warp_m * 64 + (lane >> 2);
    const int col_b = bn * 128 + warp_n * 32 + ((lane & 3) << 1);
#pragma unroll
    for (int ma = 0; ma < 4; ma++) {
#pragma unroll
        for (int na = 0; na < 4; na++) {
            float* c0 = C + (size_t)(row_b + ma * 16) * N + col_b + na * 8;
            float* c1 = c0 + (size_t)8 * N;
            *(float2*)c0 = make_float2(acc[ma][na][0], acc[ma][na][1]);
            *(float2*)c1 = make_float2(acc[ma][na][2], acc[ma][na][3]);
        }
    }
}

// ============================ elementwise / scan =============================
__device__ __forceinline__ float sigmoidf_(float v) { return 1.f / (1.f + expf(-v)); }
__device__ __forceinline__ float siluf_(float v)    { return v * sigmoidf_(v); }

__global__ __launch_bounds__(256) void conv_silu_kernel(
    const float* __restrict__ cw, const float* __restrict__ cb)
{
    const int d  = blockIdx.x * 256 + threadIdx.x;
    const int b  = blockIdx.z;
    const int t0 = blockIdx.y * 32;
    const float* xin = g_xz + (size_t)b * TLEN * (2 * DI) + d;
    float* xco = g_xconv + ((size_t)b * TLEN + t0) * DI + d;

    const float w0 = cw[d * 4 + 0], w1 = cw[d * 4 + 1];
    const float w2 = cw[d * 4 + 2], w3 = cw[d * 4 + 3];
    const float bias = cb[d];

    float xm3 = (t0 - 3 >= 0) ? xin[(size_t)(t0 - 3) * (2 * DI)] : 0.f;
    float xm2 = (t0 - 2 >= 0) ? xin[(size_t)(t0 - 2) * (2 * DI)] : 0.f;
    float xm1 = (t0 - 1 >= 0) ? xin[(size_t)(t0 - 1) * (2 * DI)] : 0.f;
#pragma unroll 4
    for (int tt = 0; tt < 32; tt++) {
        float xc = xin[(size_t)(t0 + tt) * (2 * DI)];
        float v = w0 * xm3 + w1 * xm2 + w2 * xm1 + w3 * xc + bias;
        xco[(size_t)tt * DI] = siluf_(v);
        xm3 = xm2; xm2 = xm1; xm1 = xc;
    }
}

__global__ __launch_bounds__(256) void alpha_kernel(
    const float* __restrict__ xpw, const float* __restrict__ dtw,
    const float* __restrict__ dtb)
{
    const int row = blockIdx.x;
    const int tid = threadIdx.x;
    const float* xc = g_xconv + (size_t)row * DI;

    __shared__ float bsm[DS];
    __shared__ float red[8];
    if (tid < DS) bsm[tid] = 0.f;
    __syncthreads();

    float part[DS];
#pragma unroll
    for (int n = 0; n < DS; n++) part[n] = 0.f;
    for (int d = tid; d < DI; d += 256) {
        float xv = xc[d];
#pragma unroll
        for (int n = 0; n < DS; n++) part[n] = fmaf(xv, xpw[n * DI + d], part[n]);
    }
#pragma unroll
    for (int n = 0; n < DS; n++) {
#pragma unroll
        for (int o = 16; o; o >>= 1) part[n] += __shfl_xor_sync(0xffffffffu, part[n], o);
    }
    if ((tid & 31) == 0) {
#pragma unroll
        for (int n = 0; n < DS; n++) atomicAdd(&bsm[n], part[n]);
    }
    __syncthreads();

    float lsum = 0.f;
    for (int d = tid; d < DI; d += 256) {
        float s = dtb[d];
#pragma unroll
        for (int n = 0; n < DS; n++) s = fmaf(bsm[n], dtw[d * DS + n], s);
        float sp = (s > 20.f) ? s : log1pf(expf(s));
        lsum += sp;
    }
#pragma unroll
    for (int o = 16; o; o >>= 1) lsum += __shfl_xor_sync(0xffffffffu, lsum, o);
    if ((tid & 31) == 0) red[tid >> 5] = lsum;
    __syncthreads();
    if (tid == 0) {
        float s = 0.f;
#pragma unroll
        for (int i = 0; i < 8; i++) s += red[i];
        g_alpha[row] = sigmoidf_(s / (float)DI);
    }
}

__global__ __launch_bounds__(256) void scan1_kernel()
{
    const int d = blockIdx.x * 256 + threadIdx.x;
    const int c = blockIdx.y, b = blockIdx.z;
    const float* xc = g_xconv + ((size_t)b * TLEN + c * CL) * DI + d;
    const float* al = g_alpha + b * TLEN + c * CL;
    float h = 0.f;
#pragma unroll 8
    for (int tt = 0; tt < CL; tt++) {
        float a = al[tt];
        h = fmaf(a, h, (1.f - a) * xc[(size_t)tt * DI]);
    }
    g_S[((size_t)(b * NC + c)) * DI + d] = h;
}

// cross-chunk recurrence with chunk-products computed in-block (chunkP fused).
// 32 blocks x 256: each block covers one b (DI/256 = 8 blocks per b).
__global__ __launch_bounds__(256) void scan2_kernel()
{
    const int id = blockIdx.x * 256 + threadIdx.x;
    const int b = id / DI, d = id % DI;
    __shared__ float Ps[NC];
    if (threadIdx.x < NC) {
        const float* al = g_alpha + b * TLEN + threadIdx.x * CL;
        float p = 1.f;
#pragma unroll
        for (int tt = 0; tt < CL; tt++) p *= al[tt];
        Ps[threadIdx.x] = p;
    }
    __syncthreads();
    float h = 0.f;
    g_H0[((size_t)(b * NC + 0)) * DI + d] = 0.f;
#pragma unroll 4
    for (int c = 0; c < NC - 1; c++) {
        h = fmaf(Ps[c], h, g_S[((size_t)(b * NC + c)) * DI + d]);
        g_H0[((size_t)(b * NC + c + 1)) * DI + d] = h;
    }
}

// seeded replay + D-skip + SiLU(z) gate; emits Y directly as bf16 hi/lo.
__global__ __launch_bounds__(256) void scan3_kernel(const float* __restrict__ Dp)
{
    const int d = blockIdx.x * 256 + threadIdx.x;
    const int c = blockIdx.y, b = blockIdx.z;
    const size_t rbase = (size_t)b * TLEN + c * CL;
    const float* xc = g_xconv + rbase * DI + d;
    const float* zp = g_xz + rbase * (2 * DI) + DI + d;
    const float* al = g_alpha + b * TLEN + c * CL;
    __nv_bfloat16* yh = g_yh + rbase * DI + d;
    __nv_bfloat16* yl = g_yl + rbase * DI + d;
    const float Dv = Dp[d];
    float h = g_H0[((size_t)(b * NC + c)) * DI + d];
#pragma unroll 4
    for (int tt = 0; tt < CL; tt++) {
        float a = al[tt];
        float x = xc[(size_t)tt * DI];
        h = fmaf(a, h, (1.f - a) * x);
        float y = fmaf(h, Dv, x);
        float z = zp[(size_t)tt * (2 * DI)];
        y = y * siluf_(z);
        __nv_bfloat16 hh = __float2bfloat16_rn(y);
        yh[(size_t)tt * DI] = hh;
        yl[(size_t)tt * DI] = __float2bfloat16_rn(y - __bfloat162float(hh));
    }
}

// ---------------------------------------------------------------------------
extern "C" void kernel_launch(void* const* d_in, const int* in_sizes, int n_in,
                              void* d_out, int out_size)
{
    const float* x    = (const float*)d_in[0];   // [B,T,DM]
    const float* win  = (const float*)d_in[1];   // [2*DI, DM]
    const float* cw   = (const float*)d_in[2];   // [DI,1,DC]
    const float* cb   = (const float*)d_in[3];   // [DI]
    const float* xpw  = (const float*)d_in[4];   // [2*DS, DI]
    const float* dtw  = (const float*)d_in[5];   // [DI, DS]
    const float* dtb  = (const float*)d_in[6];   // [DI]
    const float* Dp   = (const float*)d_in[7];   // [DI]
    const float* wout = (const float*)d_in[8];   // [DM, DI]
    float* out = (float*)d_out;                  // [B,T,DM]

    float* xz; cudaGetSymbolAddress((void**)&xz, g_xz);
    __nv_bfloat16 *xh, *xl, *wih, *wil, *yh, *yl, *woh, *wol;
    cudaGetSymbolAddress((void**)&xh,  g_xh);
    cudaGetSymbolAddress((void**)&xl,  g_xl);
    cudaGetSymbolAddress((void**)&wih, g_wih);
    cudaGetSymbolAddress((void**)&wil, g_wil);
    cudaGetSymbolAddress((void**)&yh,  g_yh);
    cudaGetSymbolAddress((void**)&yl,  g_yl);
    cudaGetSymbolAddress((void**)&woh, g_woh);
    cudaGetSymbolAddress((void**)&wol, g_wol);

    cudaFuncSetAttribute(gemm3_bf, cudaFuncAttributeMaxDynamicSharedMemorySize,
                         GSMEM);

    // 0) split fp32 operands into persistent bf16 hi/lo
    {
        int n4;
        n4 = (MROWS * DM) / 4;
        cvt_split_kernel<<<(n4 + 255) / 256, 256>>>(x, xh, xl, n4);
        n4 = (2 * DI * DM) / 4;
        cvt_split_kernel<<<(n4 + 255) / 256, 256>>>(win, wih, wil, n4);
        n4 = (DM * DI) / 4;
        cvt_split_kernel<<<(n4 + 255) / 256, 256>>>(wout, woh, wol, n4);
    }
    // 1) in_proj: [8192,1024] x [4096,1024]^T -> [8192,4096]
    gemm3_bf<<<dim3((2 * DI) / 128, MROWS / 128), 256, GSMEM>>>(
        xh, xl, wih, wil, xz, 2 * DI, DM);
    // 2) depthwise causal conv + SiLU
    conv_silu_kernel<<<dim3(DI / 256, TLEN / 32, BSZ), 256>>>(cw, cb);
    // 3) B_ssm + dt + alpha per row
    alpha_kernel<<<MROWS, 256>>>(xpw, dtw, dtb);
    // 4) chunked scan (chunkP fused into scan2); scan3 emits bf16 hi/lo Y
    scan1_kernel<<<dim3(DI / 256, NC, BSZ), 256>>>();
    scan2_kernel<<<MROWS / 256, 256>>>();
    scan3_kernel<<<dim3(DI / 256, NC, BSZ), 256>>>(Dp);
    // 5) out_proj: [8192,2048] x [1024,2048]^T -> [8192,1024]
    gemm3_bf<<<dim3(DM / 128, MROWS / 128), 256, GSMEM>>>(
        yh, yl, woh, wol, out, DM, DI);
}

// round 6
// speedup vs baseline: 2.1177x; 1.1408x over previous
#include <cuda_runtime.h>
#include <cuda_bf16.h>
#include <math.h>
#include <stdint.h>

// Problem constants
#define BSZ 4
#define TLEN 2048
#define DM 1024
#define DI 2048
#define DS 16
#define DC 4
#define MROWS (BSZ * TLEN)        // 8192
#define NC 64                      // scan chunks
#define CL 32                      // chunk length (NC*CL = TLEN)

// -------- scratch (device globals; allocation-free per harness rules) --------
__device__ float g_xz[(size_t)MROWS * 2 * DI];   // in_proj out (x_inner | z) fp32
__device__ float g_xconv[(size_t)MROWS * DI];    // conv+silu output (fp32)
__device__ float g_alpha[MROWS];                 // per (b,t) gate
__device__ float g_S[(size_t)BSZ * NC * DI];     // local scan end (h0=0)
__device__ float g_H0[(size_t)BSZ * NC * DI];    // chunk start state
// split-bf16 operand copies
__device__ __nv_bfloat16 g_xh[(size_t)MROWS * DM],  g_xl[(size_t)MROWS * DM];
__device__ __nv_bfloat16 g_wih[(size_t)2 * DI * DM], g_wil[(size_t)2 * DI * DM];
__device__ __nv_bfloat16 g_yh[(size_t)MROWS * DI],  g_yl[(size_t)MROWS * DI];
__device__ __nv_bfloat16 g_woh[(size_t)DM * DI],    g_wol[(size_t)DM * DI];
// bf16 single-precision paths for the rank-16 projections
__device__ __nv_bfloat16 g_xch[(size_t)MROWS * DI];  // bf16 x_conv
__device__ __nv_bfloat16 g_xpwh[(size_t)DS * DI];    // bf16 x_proj_w rows 0..15
__device__ __nv_bfloat16 g_dtwh[(size_t)DI * DS];    // bf16 dt_proj_w
__device__ __nv_bfloat16 g_Bsh[(size_t)MROWS * DS];  // bf16 B_ssm

// ============================ helpers =======================================
__device__ __forceinline__ uint32_t smem_u32(const void* p) {
    uint32_t a;
    asm("{ .reg .u64 t; cvta.to.shared.u64 t, %1; cvt.u32.u64 %0, t; }"
        : "=r"(a) : "l"(p));
    return a;
}
__device__ __forceinline__ void ldx4(uint32_t* r, uint32_t addr) {
    asm volatile("ldmatrix.sync.aligned.m8n8.x4.shared.b16 {%0,%1,%2,%3}, [%4];"
        : "=r"(r[0]), "=r"(r[1]), "=r"(r[2]), "=r"(r[3]) : "r"(addr));
}
__device__ __forceinline__ void mma16816(float* c, const uint32_t* a,
                                         uint32_t b0, uint32_t b1) {
    asm volatile(
        "mma.sync.aligned.m16n8k16.row.col.f32.bf16.bf16.f32 "
        "{%0,%1,%2,%3}, {%4,%5,%6,%7}, {%8,%9}, {%0,%1,%2,%3};"
        : "+f"(c[0]), "+f"(c[1]), "+f"(c[2]), "+f"(c[3])
        : "r"(a[0]), "r"(a[1]), "r"(a[2]), "r"(a[3]), "r"(b0), "r"(b1));
}
__device__ __forceinline__ void cp16(uint32_t s, const void* g) {
    asm volatile("cp.async.cg.shared.global [%0], [%1], 16;"
        :: "r"(s), "l"(g) : "memory");
}
__device__ __forceinline__ float sigmoidf_(float v) { return 1.f / (1.f + __expf(-v)); }
__device__ __forceinline__ float siluf_(float v)    { return v * sigmoidf_(v); }
__device__ __forceinline__ float softplusf_(float v) {
    return (v > 20.f) ? v : __logf(1.f + __expf(v));
}
__device__ __forceinline__ uint32_t packbf2(float a, float b) {
    __nv_bfloat162 t = __floats2bfloat162_rn(a, b);
    return *(uint32_t*)&t;
}

// ---------------------------------------------------------------------------
// fp32 -> (hi, lo) bf16 split; and hi-only variant. n divisible by 4.
// ---------------------------------------------------------------------------
__global__ __launch_bounds__(256) void cvt_split_kernel(
    const float* __restrict__ src, __nv_bfloat16* __restrict__ hi,
    __nv_bfloat16* __restrict__ lo, int n4)
{
    int i = blockIdx.x * 256 + threadIdx.x;
    if (i >= n4) return;
    float4 v = ((const float4*)src)[i];
    float vv[4] = {v.x, v.y, v.z, v.w};
    __nv_bfloat16 h[4], l[4];
#pragma unroll
    for (int k = 0; k < 4; k++) {
        h[k] = __float2bfloat16_rn(vv[k]);
        l[k] = __float2bfloat16_rn(vv[k] - __bfloat162float(h[k]));
    }
    ((uint2*)hi)[i] = *(uint2*)h;
    ((uint2*)lo)[i] = *(uint2*)l;
}

__global__ __launch_bounds__(256) void cvt_h_kernel(
    const float* __restrict__ src, __nv_bfloat16* __restrict__ hi, int n4)
{
    int i = blockIdx.x * 256 + threadIdx.x;
    if (i >= n4) return;
    float4 v = ((const float4*)src)[i];
    __nv_bfloat16 h[4] = {
        __float2bfloat16_rn(v.x), __float2bfloat16_rn(v.y),
        __float2bfloat16_rn(v.z), __float2bfloat16_rn(v.w)};
    ((uint2*)hi)[i] = *(uint2*)h;
}

// ---------------------------------------------------------------------------
// Split-bf16 NT GEMM via mma.sync (3-term, term-major issue order).
// ---------------------------------------------------------------------------
#define KC    32
#define ROWB  80
#define TILEB (128 * ROWB)
#define STGB  (4 * TILEB)
#define GSMEM (2 * STGB)

__global__ __launch_bounds__(256) void gemm3_bf(
    const __nv_bfloat16* __restrict__ Ah_, const __nv_bfloat16* __restrict__ Al_,
    const __nv_bfloat16* __restrict__ Bh_, const __nv_bfloat16* __restrict__ Bl_,
    float* __restrict__ C, int N, int K)
{
    extern __shared__ char smem[];
    const uint32_t sb = smem_u32(smem);
    const int tid = threadIdx.x, lane = tid & 31, wid = tid >> 5;
    const int bm = blockIdx.y, bn = blockIdx.x;
    const int warp_m = wid >> 2, warp_n = wid & 3;

    const int r = tid >> 1, half = tid & 1;
    const size_t arow = (size_t)(bm * 128 + r) * K;
    const size_t brow = (size_t)(bn * 128 + r) * K;
    const uint32_t soff = (uint32_t)(r * ROWB + half * 32);

    float acc[4][4][4];
#pragma unroll
    for (int i = 0; i < 4; i++)
#pragma unroll
        for (int j = 0; j < 4; j++)
#pragma unroll
            for (int q = 0; q < 4; q++) acc[i][j][q] = 0.f;

    const int nch = K / KC;

#define ISSUE(ch) do { \
        uint32_t dst = sb + (uint32_t)((ch) & 1) * STGB + soff; \
        size_t koff = (size_t)(ch) * KC + half * 16; \
        cp16(dst + 0 * TILEB,      Ah_ + arow + koff); \
        cp16(dst + 0 * TILEB + 16, Ah_ + arow + koff + 8); \
        cp16(dst + 1 * TILEB,      Al_ + arow + koff); \
        cp16(dst + 1 * TILEB + 16, Al_ + arow + koff + 8); \
        cp16(dst + 2 * TILEB,      Bh_ + brow + koff); \
        cp16(dst + 2 * TILEB + 16, Bh_ + brow + koff + 8); \
        cp16(dst + 3 * TILEB,      Bl_ + brow + koff); \
        cp16(dst + 3 * TILEB + 16, Bl_ + brow + koff + 8); \
        asm volatile("cp.async.commit_group;" ::: "memory"); \
    } while (0)

    ISSUE(0);
    ISSUE(1);

    const uint32_t lrow = lane & 15, lcolb = (lane >> 4) * 16;
    const uint32_t a_lm = (uint32_t)((warp_m * 64 + lrow) * ROWB) + lcolb;
    const uint32_t b_lm = (uint32_t)((warp_n * 32 + lrow) * ROWB) + lcolb;

    for (int ch = 0; ch < nch; ch++) {
        if (ch + 1 < nch)
            asm volatile("cp.async.wait_group 1;" ::: "memory");
        else
            asm volatile("cp.async.wait_group 0;" ::: "memory");
        __syncthreads();

        const uint32_t st = sb + (uint32_t)(ch & 1) * STGB;
#pragma unroll
        for (int ks = 0; ks < 2; ks++) {
            uint32_t Ah[4][4], Al[4][4], Bh[4][2], Bl[4][2];
#pragma unroll
            for (int ma = 0; ma < 4; ma++) {
                uint32_t ad = st + a_lm + (uint32_t)(ma * 16 * ROWB) + ks * 32;
                ldx4(Ah[ma], ad);
                ldx4(Al[ma], ad + TILEB);
            }
#pragma unroll
            for (int p = 0; p < 2; p++) {
                uint32_t bd = st + 2 * TILEB + b_lm + (uint32_t)(p * 16 * ROWB) + ks * 32;
                uint32_t q[4];
                ldx4(q, bd);
                Bh[2 * p][0] = q[0]; Bh[2 * p][1] = q[2];
                Bh[2 * p + 1][0] = q[1]; Bh[2 * p + 1][1] = q[3];
                ldx4(q, bd + TILEB);
                Bl[2 * p][0] = q[0]; Bl[2 * p][1] = q[2];
                Bl[2 * p + 1][0] = q[1]; Bl[2 * p + 1][1] = q[3];
            }
            // term-major: accumulator reuse distance = 16 MMAs
#pragma unroll
            for (int ma = 0; ma < 4; ma++)
#pragma unroll
                for (int na = 0; na < 4; na++)
                    mma16816(acc[ma][na], Ah[ma], Bh[na][0], Bh[na][1]);
#pragma unroll
            for (int ma = 0; ma < 4; ma++)
#pragma unroll
                for (int na = 0; na < 4; na++)
                    mma16816(acc[ma][na], Al[ma], Bh[na][0], Bh[na][1]);
#pragma unroll
            for (int ma = 0; ma < 4; ma++)
#pragma unroll
                for (int na = 0; na < 4; na++)
                    mma16816(acc[ma][na], Ah[ma], Bl[na][0], Bl[na][1]);
        }
        __syncthreads();
        if (ch + 2 < nch) ISSUE(ch + 2);
    }
#undef ISSUE

    const int row_b = bm * 128 + warp_m * 64 + (lane >> 2);
    const int col_b = bn * 128 + warp_n * 32 + ((lane & 3) << 1);
#pragma unroll
    for (int ma = 0; ma < 4; ma++) {
#pragma unroll
        for (int na = 0; na < 4; na++) {
            float* c0 = C + (size_t)(row_b + ma * 16) * N + col_b + na * 8;
            float* c1 = c0 + (size_t)8 * N;
            *(float2*)c0 = make_float2(acc[ma][na][0], acc[ma][na][1]);
            *(float2*)c1 = make_float2(acc[ma][na][2], acc[ma][na][3]);
        }
    }
}

// ============================ elementwise / scan =============================
__global__ __launch_bounds__(256) void conv_silu_kernel(
    const float* __restrict__ cw, const float* __restrict__ cb)
{
    const int d  = blockIdx.x * 256 + threadIdx.x;
    const int b  = blockIdx.z;
    const int t0 = blockIdx.y * 32;
    const float* xin = g_xz + (size_t)b * TLEN * (2 * DI) + d;
    float* xco = g_xconv + ((size_t)b * TLEN + t0) * DI + d;
    __nv_bfloat16* xch = g_xch + ((size_t)b * TLEN + t0) * DI + d;

    const float w0 = cw[d * 4 + 0], w1 = cw[d * 4 + 1];
    const float w2 = cw[d * 4 + 2], w3 = cw[d * 4 + 3];
    const float bias = cb[d];

    float xm3 = (t0 - 3 >= 0) ? xin[(size_t)(t0 - 3) * (2 * DI)] : 0.f;
    float xm2 = (t0 - 2 >= 0) ? xin[(size_t)(t0 - 2) * (2 * DI)] : 0.f;
    float xm1 = (t0 - 1 >= 0) ? xin[(size_t)(t0 - 1) * (2 * DI)] : 0.f;
#pragma unroll 4
    for (int tt = 0; tt < 32; tt++) {
        float xc = xin[(size_t)(t0 + tt) * (2 * DI)];
        float v = w0 * xm3 + w1 * xm2 + w2 * xm1 + w3 * xc + bias;
        float s = siluf_(v);
        xco[(size_t)tt * DI] = s;
        xch[(size_t)tt * DI] = __float2bfloat16_rn(s);
        xm3 = xm2; xm2 = xm1; xm1 = xc;
    }
}

// B_ssm[8192,16] = xch[8192,2048] x xpwh[16,2048]^T  via mma.sync.
// Warp per 16 rows; manual fragment loads from GMEM. Writes bf16 B_ssm.
__global__ __launch_bounds__(256) void proj16_kernel()
{
    const int lane = threadIdx.x & 31, wid = threadIdx.x >> 5;
    const int rowbase = (blockIdx.x * 8 + wid) * 16;
    const int r0 = rowbase + (lane >> 2);
    const int k0l = (lane & 3) * 2;
    const __nv_bfloat16* xr0 = g_xch + (size_t)r0 * DI;
    const __nv_bfloat16* xr8 = xr0 + (size_t)8 * DI;
    const int nfr = (lane >> 2);   // b-frag n = l/4

    float c[2][4];
#pragma unroll
    for (int nt = 0; nt < 2; nt++)
#pragma unroll
        for (int q = 0; q < 4; q++) c[nt][q] = 0.f;

    for (int ks = 0; ks < DI / 16; ks++) {
        const int k0 = ks * 16 + k0l;
        uint32_t a[4];
        a[0] = *(const uint32_t*)(xr0 + k0);
        a[1] = *(const uint32_t*)(xr8 + k0);
        a[2] = *(const uint32_t*)(xr0 + k0 + 8);
        a[3] = *(const uint32_t*)(xr8 + k0 + 8);
#pragma unroll
        for (int nt = 0; nt < 2; nt++) {
            const __nv_bfloat16* wn = g_xpwh + (size_t)(nt * 8 + nfr) * DI + k0;
            uint32_t b0 = *(const uint32_t*)(wn);
            uint32_t b1 = *(const uint32_t*)(wn + 8);
            mma16816(c[nt], a, b0, b1);
        }
    }
    // write bf16 B_ssm: lane covers rows r0, r0+8; cols (l&3)*2 + nt*8
#pragma unroll
    for (int nt = 0; nt < 2; nt++) {
        uint32_t* p0 = (uint32_t*)(g_Bsh + (size_t)r0 * DS + nt * 8 + k0l);
        uint32_t* p1 = (uint32_t*)(g_Bsh + (size_t)(r0 + 8) * DS + nt * 8 + k0l);
        *p0 = packbf2(c[nt][0], c[nt][1]);
        *p1 = packbf2(c[nt][2], c[nt][3]);
    }
}

// alpha[row] = sigmoid(mean_d softplus(Bssm . dtw[d] + dtb[d])) via mma.sync.
// Warp per 16 rows; K=16 (single k-step); fused softplus + mean epilogue.
__global__ __launch_bounds__(256) void alphaB_kernel(const float* __restrict__ dtb)
{
    const int lane = threadIdx.x & 31, wid = threadIdx.x >> 5;
    const int rowbase = (blockIdx.x * 8 + wid) * 16;
    const int r0 = rowbase + (lane >> 2);
    const int k0l = (lane & 3) * 2;
    const int nfr = (lane >> 2);

    uint32_t a[4];
    a[0] = *(const uint32_t*)(g_Bsh + (size_t)r0 * DS + k0l);
    a[1] = *(const uint32_t*)(g_Bsh + (size_t)(r0 + 8) * DS + k0l);
    a[2] = *(const uint32_t*)(g_Bsh + (size_t)r0 * DS + k0l + 8);
    a[3] = *(const uint32_t*)(g_Bsh + (size_t)(r0 + 8) * DS + k0l + 8);

    float sumA = 0.f, sumB = 0.f;
    for (int nd = 0; nd < DI / 8; nd++) {
        const int n = nd * 8 + nfr;
        const __nv_bfloat16* wn = g_dtwh + (size_t)n * DS;
        uint32_t b0 = *(const uint32_t*)(wn + k0l);
        uint32_t b1 = *(const uint32_t*)(wn + k0l + 8);
        float c[4] = {0.f, 0.f, 0.f, 0.f};
        mma16816(c, a, b0, b1);
        const int nc = nd * 8 + k0l;
        float bb0 = dtb[nc], bb1 = dtb[nc + 1];
        sumA += softplusf_(c[0] + bb0) + softplusf_(c[1] + bb1);
        sumB += softplusf_(c[2] + bb0) + softplusf_(c[3] + bb1);
    }
    sumA += __shfl_xor_sync(0xffffffffu, sumA, 1);
    sumA += __shfl_xor_sync(0xffffffffu, sumA, 2);
    sumB += __shfl_xor_sync(0xffffffffu, sumB, 1);
    sumB += __shfl_xor_sync(0xffffffffu, sumB, 2);
    if ((lane & 3) == 0) {
        g_alpha[r0]     = sigmoidf_(sumA * (1.f / (float)DI));
        g_alpha[r0 + 8] = sigmoidf_(sumB * (1.f / (float)DI));
    }
}

__global__ __launch_bounds__(256) void scan1_kernel()
{
    const int d = blockIdx.x * 256 + threadIdx.x;
    const int c = blockIdx.y, b = blockIdx.z;
    const float* xc = g_xconv + ((size_t)b * TLEN + c * CL) * DI + d;
    const float* al = g_alpha + b * TLEN + c * CL;
    float h = 0.f;
#pragma unroll 8
    for (int tt = 0; tt < CL; tt++) {
        float a = al[tt];
        h = fmaf(a, h, (1.f - a) * xc[(size_t)tt * DI]);
    }
    g_S[((size_t)(b * NC + c)) * DI + d] = h;
}

__global__ __launch_bounds__(256) void scan2_kernel()
{
    const int id = blockIdx.x * 256 + threadIdx.x;
    const int b = id / DI, d = id % DI;
    __shared__ float Ps[NC];
    if (threadIdx.x < NC) {
        const float* al = g_alpha + b * TLEN + threadIdx.x * CL;
        float p = 1.f;
#pragma unroll
        for (int tt = 0; tt < CL; tt++) p *= al[tt];
        Ps[threadIdx.x] = p;
    }
    __syncthreads();
    float h = 0.f;
    g_H0[((size_t)(b * NC + 0)) * DI + d] = 0.f;
#pragma unroll 4
    for (int c = 0; c < NC - 1; c++) {
        h = fmaf(Ps[c], h, g_S[((size_t)(b * NC + c)) * DI + d]);
        g_H0[((size_t)(b * NC + c + 1)) * DI + d] = h;
    }
}

__global__ __launch_bounds__(256) void scan3_kernel(const float* __restrict__ Dp)
{
    const int d = blockIdx.x * 256 + threadIdx.x;
    const int c = blockIdx.y, b = blockIdx.z;
    const size_t rbase = (size_t)b * TLEN + c * CL;
    const float* xc = g_xconv + rbase * DI + d;
    const float* zp = g_xz + rbase * (2 * DI) + DI + d;
    const float* al = g_alpha + b * TLEN + c * CL;
    __nv_bfloat16* yh = g_yh + rbase * DI + d;
    __nv_bfloat16* yl = g_yl + rbase * DI + d;
    const float Dv = Dp[d];
    float h = g_H0[((size_t)(b * NC + c)) * DI + d];
#pragma unroll 4
    for (int tt = 0; tt < CL; tt++) {
        float a = al[tt];
        float x = xc[(size_t)tt * DI];
        h = fmaf(a, h, (1.f - a) * x);
        float y = fmaf(h, Dv, x);
        float z = zp[(size_t)tt * (2 * DI)];
        y = y * siluf_(z);
        __nv_bfloat16 hh = __float2bfloat16_rn(y);
        yh[(size_t)tt * DI] = hh;
        yl[(size_t)tt * DI] = __float2bfloat16_rn(y - __bfloat162float(hh));
    }
}

// ---------------------------------------------------------------------------
extern "C" void kernel_launch(void* const* d_in, const int* in_sizes, int n_in,
                              void* d_out, int out_size)
{
    const float* x    = (const float*)d_in[0];   // [B,T,DM]
    const float* win  = (const float*)d_in[1];   // [2*DI, DM]
    const float* cw   = (const float*)d_in[2];   // [DI,1,DC]
    const float* cb   = (const float*)d_in[3];   // [DI]
    const float* xpw  = (const float*)d_in[4];   // [2*DS, DI]
    const float* dtw  = (const float*)d_in[5];   // [DI, DS]
    const float* dtb  = (const float*)d_in[6];   // [DI]
    const float* Dp   = (const float*)d_in[7];   // [DI]
    const float* wout = (const float*)d_in[8];   // [DM, DI]
    float* out = (float*)d_out;                  // [B,T,DM]

    float* xz; cudaGetSymbolAddress((void**)&xz, g_xz);
    __nv_bfloat16 *xh, *xl, *wih, *wil, *yh, *yl, *woh, *wol, *xpwh, *dtwh;
    cudaGetSymbolAddress((void**)&xh,   g_xh);
    cudaGetSymbolAddress((void**)&xl,   g_xl);
    cudaGetSymbolAddress((void**)&wih,  g_wih);
    cudaGetSymbolAddress((void**)&wil,  g_wil);
    cudaGetSymbolAddress((void**)&yh,   g_yh);
    cudaGetSymbolAddress((void**)&yl,   g_yl);
    cudaGetSymbolAddress((void**)&woh,  g_woh);
    cudaGetSymbolAddress((void**)&wol,  g_wol);
    cudaGetSymbolAddress((void**)&xpwh, g_xpwh);
    cudaGetSymbolAddress((void**)&dtwh, g_dtwh);

    cudaFuncSetAttribute(gemm3_bf, cudaFuncAttributeMaxDynamicSharedMemorySize,
                         GSMEM);

    // 0) operand conversions
    {
        int n4;
        n4 = (MROWS * DM) / 4;
        cvt_split_kernel<<<(n4 + 255) / 256, 256>>>(x, xh, xl, n4);
        n4 = (2 * DI * DM) / 4;
        cvt_split_kernel<<<(n4 + 255) / 256, 256>>>(win, wih, wil, n4);
        n4 = (DM * DI) / 4;
        cvt_split_kernel<<<(n4 + 255) / 256, 256>>>(wout, woh, wol, n4);
        n4 = (DS * DI) / 4;
        cvt_h_kernel<<<(n4 + 255) / 256, 256>>>(xpw, xpwh, n4);   // rows 0..15
        n4 = (DI * DS) / 4;
        cvt_h_kernel<<<(n4 + 255) / 256, 256>>>(dtw, dtwh, n4);
    }
    // 1) in_proj
    gemm3_bf<<<dim3((2 * DI) / 128, MROWS / 128), 256, GSMEM>>>(
        xh, xl, wih, wil, xz, 2 * DI, DM);
    // 2) depthwise causal conv + SiLU (fp32 + bf16 copies)
    conv_silu_kernel<<<dim3(DI / 256, TLEN / 32, BSZ), 256>>>(cw, cb);
    // 3) B_ssm + alpha (tensor-core rank-16 projections)
    proj16_kernel<<<MROWS / 128, 256>>>();
    alphaB_kernel<<<MROWS / 128, 256>>>(dtb);
    // 4) chunked scan
    scan1_kernel<<<dim3(DI / 256, NC, BSZ), 256>>>();
    scan2_kernel<<<MROWS / 256, 256>>>();
    scan3_kernel<<<dim3(DI / 256, NC, BSZ), 256>>>(Dp);
    // 5) out_proj
    gemm3_bf<<<dim3(DM / 128, MROWS / 128), 256, GSMEM>>>(
        yh, yl, woh, wol, out, DM, DI);
}

// round 7
// speedup vs baseline: 2.5554x; 1.2067x over previous
#include <cuda_runtime.h>
#include <cuda_bf16.h>
#include <math.h>
#include <stdint.h>

// Problem constants
#define BSZ 4
#define TLEN 2048
#define DM 1024
#define DI 2048
#define DS 16
#define DC 4
#define MROWS (BSZ * TLEN)        // 8192
#define NC 64                      // scan chunks
#define CL 32                      // chunk length

// -------- scratch (device globals) --------
__device__ float g_xz[(size_t)MROWS * 2 * DI];
__device__ float g_xconv[(size_t)MROWS * DI];
__device__ float g_alpha[MROWS];
__device__ float g_S[(size_t)BSZ * NC * DI];
__device__ float g_H0[(size_t)BSZ * NC * DI];
__device__ __nv_bfloat16 g_xh[(size_t)MROWS * DM],  g_xl[(size_t)MROWS * DM];
__device__ __nv_bfloat16 g_wih[(size_t)2 * DI * DM], g_wil[(size_t)2 * DI * DM];
__device__ __nv_bfloat16 g_yh[(size_t)MROWS * DI],  g_yl[(size_t)MROWS * DI];
__device__ __nv_bfloat16 g_woh[(size_t)DM * DI],    g_wol[(size_t)DM * DI];
__device__ __nv_bfloat16 g_xch[(size_t)MROWS * DI];
__device__ __nv_bfloat16 g_xpwh[(size_t)DS * DI];
__device__ __nv_bfloat16 g_dtwh[(size_t)DI * DS];

// ============================ helpers =======================================
__device__ __forceinline__ uint32_t smem_u32(const void* p) {
    uint32_t a;
    asm("{ .reg .u64 t; cvta.to.shared.u64 t, %1; cvt.u32.u64 %0, t; }"
        : "=r"(a) : "l"(p));
    return a;
}
__device__ __forceinline__ void ldx4(uint32_t* r, uint32_t addr) {
    asm volatile("ldmatrix.sync.aligned.m8n8.x4.shared.b16 {%0,%1,%2,%3}, [%4];"
        : "=r"(r[0]), "=r"(r[1]), "=r"(r[2]), "=r"(r[3]) : "r"(addr));
}
__device__ __forceinline__ void mma16816(float* c, const uint32_t* a,
                                         uint32_t b0, uint32_t b1) {
    asm volatile(
        "mma.sync.aligned.m16n8k16.row.col.f32.bf16.bf16.f32 "
        "{%0,%1,%2,%3}, {%4,%5,%6,%7}, {%8,%9}, {%0,%1,%2,%3};"
        : "+f"(c[0]), "+f"(c[1]), "+f"(c[2]), "+f"(c[3])
        : "r"(a[0]), "r"(a[1]), "r"(a[2]), "r"(a[3]), "r"(b0), "r"(b1));
}
__device__ __forceinline__ void cp16(uint32_t s, const void* g) {
    asm volatile("cp.async.cg.shared.global [%0], [%1], 16;"
        :: "r"(s), "l"(g) : "memory");
}
__device__ __forceinline__ float sigmoidf_(float v) { return 1.f / (1.f + __expf(-v)); }
__device__ __forceinline__ float siluf_(float v)    { return v * sigmoidf_(v); }
__device__ __forceinline__ float softplusf_(float v) {
    return (v > 20.f) ? v : __logf(1.f + __expf(v));
}
__device__ __forceinline__ uint32_t packbf2(float a, float b) {
    __nv_bfloat162 t = __floats2bfloat162_rn(a, b);
    return *(uint32_t*)&t;
}
// SW64-style swizzle for 64B rows (8192B tile, base 8192-aligned)
__device__ __forceinline__ uint32_t swz64(uint32_t o) {
    return o ^ ((o >> 3) & 0x30);
}

// ---------------------------------------------------------------------------
// Merged operand conversion: x/win/wout split hi+lo; xpw/dtw hi only.
// ---------------------------------------------------------------------------
#define CV_N0 (MROWS * DM / 4)
#define CV_N1 (CV_N0 + 2 * DI * DM / 4)
#define CV_N2 (CV_N1 + DM * DI / 4)
#define CV_N3 (CV_N2 + DS * DI / 4)
#define CV_N4 (CV_N3 + DI * DS / 4)

__global__ __launch_bounds__(256) void cvt_all_kernel(
    const float* __restrict__ x, const float* __restrict__ win,
    const float* __restrict__ wout, const float* __restrict__ xpw,
    const float* __restrict__ dtw)
{
    int i = blockIdx.x * 256 + threadIdx.x;
    if (i >= CV_N4) return;
    const float* src; __nv_bfloat16 *hi, *lo; int j; bool split = true;
    if (i < CV_N0)      { j = i;         src = x;    hi = g_xh;  lo = g_xl;  }
    else if (i < CV_N1) { j = i - CV_N0; src = win;  hi = g_wih; lo = g_wil; }
    else if (i < CV_N2) { j = i - CV_N1; src = wout; hi = g_woh; lo = g_wol; }
    else if (i < CV_N3) { j = i - CV_N2; src = xpw;  hi = g_xpwh; lo = 0; split = false; }
    else                { j = i - CV_N3; src = dtw;  hi = g_dtwh; lo = 0; split = false; }
    float4 v = ((const float4*)src)[j];
    float vv[4] = {v.x, v.y, v.z, v.w};
    __nv_bfloat16 h[4], l[4];
#pragma unroll
    for (int k = 0; k < 4; k++) {
        h[k] = __float2bfloat16_rn(vv[k]);
        l[k] = __float2bfloat16_rn(vv[k] - __bfloat162float(h[k]));
    }
    ((uint2*)hi)[j] = *(uint2*)h;
    if (split) ((uint2*)lo)[j] = *(uint2*)l;
}

// ---------------------------------------------------------------------------
// Split-bf16 NT GEMM via mma.sync: 3-stage cp.async pipeline, swizzled SMEM,
// one barrier per chunk, term-major MMA order. 2 CTAs/SM.
// ---------------------------------------------------------------------------
#define KC    32
#define TILEB 8192                 // 128 rows x 64B, swizzled
#define STGB  (4 * TILEB)          // Ah, Al, Bh, Bl = 32768
#define NSTG  3
#define GSMEM (NSTG * STGB)        // 98304

__global__ void __launch_bounds__(256, 2) gemm3_bf(
    const __nv_bfloat16* __restrict__ Ah_, const __nv_bfloat16* __restrict__ Al_,
    const __nv_bfloat16* __restrict__ Bh_, const __nv_bfloat16* __restrict__ Bl_,
    float* __restrict__ C, int N, int K)
{
    extern __shared__ char smem[];
    const uint32_t sb = smem_u32(smem);
    const int tid = threadIdx.x, lane = tid & 31, wid = tid >> 5;
    const int bm = blockIdx.y, bn = blockIdx.x;
    const int warp_m = wid >> 2, warp_n = wid & 3;

    const int r = tid >> 1, half = tid & 1;
    const size_t arow = (size_t)(bm * 128 + r) * K;
    const size_t brow = (size_t)(bn * 128 + r) * K;
    const uint32_t lo_log = (uint32_t)(r * 64 + half * 32);
    const uint32_t d0 = swz64(lo_log), d1 = swz64(lo_log + 16);

    float acc[4][4][4];
#pragma unroll
    for (int i = 0; i < 4; i++)
#pragma unroll
        for (int j = 0; j < 4; j++)
#pragma unroll
            for (int q = 0; q < 4; q++) acc[i][j][q] = 0.f;

    const int nch = K / KC;

#define ISSUE(ch, stg) do { \
        uint32_t dst = sb + (uint32_t)(stg) * STGB; \
        size_t koff = (size_t)(ch) * KC + half * 16; \
        cp16(dst + 0 * TILEB + d0, Ah_ + arow + koff); \
        cp16(dst + 0 * TILEB + d1, Ah_ + arow + koff + 8); \
        cp16(dst + 1 * TILEB + d0, Al_ + arow + koff); \
        cp16(dst + 1 * TILEB + d1, Al_ + arow + koff + 8); \
        cp16(dst + 2 * TILEB + d0, Bh_ + brow + koff); \
        cp16(dst + 2 * TILEB + d1, Bh_ + brow + koff + 8); \
        cp16(dst + 3 * TILEB + d0, Bl_ + brow + koff); \
        cp16(dst + 3 * TILEB + d1, Bl_ + brow + koff + 8); \
        asm volatile("cp.async.commit_group;" ::: "memory"); \
    } while (0)

    ISSUE(0, 0);
    ISSUE(1, 1);

    const uint32_t lrow = lane & 15, lcolb = (lane >> 4) * 16;

    int cs = 0, is = 2;   // compute stage, issue stage (mod 3)
    for (int ch = 0; ch < nch; ch++) {
        if (ch + 1 < nch)
            asm volatile("cp.async.wait_group 1;" ::: "memory");
        else
            asm volatile("cp.async.wait_group 0;" ::: "memory");
        __syncthreads();
        if (ch + 2 < nch) {
            ISSUE(ch + 2, is);
            is = (is == 2) ? 0 : is + 1;
        }

        const uint32_t st = sb + (uint32_t)cs * STGB;
        cs = (cs == 2) ? 0 : cs + 1;
#pragma unroll
        for (int ks = 0; ks < 2; ks++) {
            uint32_t Ah[4][4], Al[4][4], Bh[4][2], Bl[4][2];
#pragma unroll
            for (int ma = 0; ma < 4; ma++) {
                uint32_t alog = (uint32_t)((warp_m * 64 + ma * 16 + lrow) * 64
                                           + ks * 32) + lcolb;
                uint32_t ad = st + swz64(alog);
                ldx4(Ah[ma], ad);
                ldx4(Al[ma], ad + TILEB);
            }
#pragma unroll
            for (int p = 0; p < 2; p++) {
                uint32_t blog = (uint32_t)((warp_n * 32 + p * 16 + lrow) * 64
                                           + ks * 32) + lcolb;
                uint32_t bd = st + 2 * TILEB + swz64(blog);
                uint32_t q[4];
                ldx4(q, bd);
                Bh[2 * p][0] = q[0]; Bh[2 * p][1] = q[2];
                Bh[2 * p + 1][0] = q[1]; Bh[2 * p + 1][1] = q[3];
                ldx4(q, bd + TILEB);
                Bl[2 * p][0] = q[0]; Bl[2 * p][1] = q[2];
                Bl[2 * p + 1][0] = q[1]; Bl[2 * p + 1][1] = q[3];
            }
#pragma unroll
            for (int ma = 0; ma < 4; ma++)
#pragma unroll
                for (int na = 0; na < 4; na++)
                    mma16816(acc[ma][na], Ah[ma], Bh[na][0], Bh[na][1]);
#pragma unroll
            for (int ma = 0; ma < 4; ma++)
#pragma unroll
                for (int na = 0; na < 4; na++)
                    mma16816(acc[ma][na], Al[ma], Bh[na][0], Bh[na][1]);
#pragma unroll
            for (int ma = 0; ma < 4; ma++)
#pragma unroll
                for (int na = 0; na < 4; na++)
                    mma16816(acc[ma][na], Ah[ma], Bl[na][0], Bl[na][1]);
        }
    }
#undef ISSUE

    const int row_b = bm * 128 + warp_m * 64 + (lane >> 2);
    const int col_b = bn * 128 + warp_n * 32 + ((lane & 3) << 1);
#pragma unroll
    for (int ma = 0; ma < 4; ma++) {
#pragma unroll
        for (int na = 0; na < 4; na++) {
            float* c0 = C + (size_t)(row_b + ma * 16) * N + col_b + na * 8;
            float* c1 = c0 + (size_t)8 * N;
            *(float2*)c0 = make_float2(acc[ma][na][0], acc[ma][na][1]);
            *(float2*)c1 = make_float2(acc[ma][na][2], acc[ma][na][3]);
        }
    }
}

// ============================ elementwise / scan =============================
__global__ __launch_bounds__(256) void conv_silu_kernel(
    const float* __restrict__ cw, const float* __restrict__ cb)
{
    const int d  = blockIdx.x * 256 + threadIdx.x;
    const int b  = blockIdx.z;
    const int t0 = blockIdx.y * 32;
    const float* xin = g_xz + (size_t)b * TLEN * (2 * DI) + d;
    float* xco = g_xconv + ((size_t)b * TLEN + t0) * DI + d;
    __nv_bfloat16* xch = g_xch + ((size_t)b * TLEN + t0) * DI + d;

    const float w0 = cw[d * 4 + 0], w1 = cw[d * 4 + 1];
    const float w2 = cw[d * 4 + 2], w3 = cw[d * 4 + 3];
    const float bias = cb[d];

    float xm3 = (t0 - 3 >= 0) ? xin[(size_t)(t0 - 3) * (2 * DI)] : 0.f;
    float xm2 = (t0 - 2 >= 0) ? xin[(size_t)(t0 - 2) * (2 * DI)] : 0.f;
    float xm1 = (t0 - 1 >= 0) ? xin[(size_t)(t0 - 1) * (2 * DI)] : 0.f;
#pragma unroll 4
    for (int tt = 0; tt < 32; tt++) {
        float xc = xin[(size_t)(t0 + tt) * (2 * DI)];
        float v = w0 * xm3 + w1 * xm2 + w2 * xm1 + w3 * xc + bias;
        float s = siluf_(v);
        xco[(size_t)tt * DI] = s;
        xch[(size_t)tt * DI] = __float2bfloat16_rn(s);
        xm3 = xm2; xm2 = xm1; xm1 = xc;
    }
}

// Fused: B_ssm (rank-16 MMA over K=2048) -> dt MMA -> softplus/mean/sigmoid.
// Warp per 16 rows; B_ssm stays in registers (C-frag == next A-frag layout).
__global__ __launch_bounds__(256) void proj_alpha_kernel(const float* __restrict__ dtb)
{
    const int lane = threadIdx.x & 31, wid = threadIdx.x >> 5;
    const int rowbase = (blockIdx.x * 8 + wid) * 16;
    const int r0 = rowbase + (lane >> 2);
    const int k0l = (lane & 3) * 2;
    const int nfr = (lane >> 2);
    const __nv_bfloat16* xr0 = g_xch + (size_t)r0 * DI;
    const __nv_bfloat16* xr8 = xr0 + (size_t)8 * DI;

    float c[2][4];
#pragma unroll
    for (int nt = 0; nt < 2; nt++)
#pragma unroll
        for (int q = 0; q < 4; q++) c[nt][q] = 0.f;

    for (int ks = 0; ks < DI / 16; ks++) {
        const int k0 = ks * 16 + k0l;
        uint32_t a[4];
        a[0] = *(const uint32_t*)(xr0 + k0);
        a[1] = *(const uint32_t*)(xr8 + k0);
        a[2] = *(const uint32_t*)(xr0 + k0 + 8);
        a[3] = *(const uint32_t*)(xr8 + k0 + 8);
#pragma unroll
        for (int nt = 0; nt < 2; nt++) {
            const __nv_bfloat16* wn = g_xpwh + (size_t)(nt * 8 + nfr) * DI + k0;
            uint32_t b0 = *(const uint32_t*)(wn);
            uint32_t b1 = *(const uint32_t*)(wn + 8);
            mma16816(c[nt], a, b0, b1);
        }
    }
    // B_ssm C-fragment -> A-fragment for the dt MMA (same lane mapping)
    uint32_t a2[4];
    a2[0] = packbf2(c[0][0], c[0][1]);
    a2[1] = packbf2(c[0][2], c[0][3]);
    a2[2] = packbf2(c[1][0], c[1][1]);
    a2[3] = packbf2(c[1][2], c[1][3]);

    float sumA = 0.f, sumB = 0.f;
    for (int nd = 0; nd < DI / 8; nd++) {
        const int n = nd * 8 + nfr;
        const __nv_bfloat16* wn = g_dtwh + (size_t)n * DS;
        uint32_t b0 = *(const uint32_t*)(wn + k0l);
        uint32_t b1 = *(const uint32_t*)(wn + k0l + 8);
        float cc[4] = {0.f, 0.f, 0.f, 0.f};
        mma16816(cc, a2, b0, b1);
        const int ncx = nd * 8 + k0l;
        float bb0 = dtb[ncx], bb1 = dtb[ncx + 1];
        sumA += softplusf_(cc[0] + bb0) + softplusf_(cc[1] + bb1);
        sumB += softplusf_(cc[2] + bb0) + softplusf_(cc[3] + bb1);
    }
    sumA += __shfl_xor_sync(0xffffffffu, sumA, 1);
    sumA += __shfl_xor_sync(0xffffffffu, sumA, 2);
    sumB += __shfl_xor_sync(0xffffffffu, sumB, 1);
    sumB += __shfl_xor_sync(0xffffffffu, sumB, 2);
    if ((lane & 3) == 0) {
        g_alpha[r0]     = sigmoidf_(sumA * (1.f / (float)DI));
        g_alpha[r0 + 8] = sigmoidf_(sumB * (1.f / (float)DI));
    }
}

__global__ __launch_bounds__(256) void scan1_kernel()
{
    const int d = blockIdx.x * 256 + threadIdx.x;
    const int c = blockIdx.y, b = blockIdx.z;
    const float* xc = g_xconv + ((size_t)b * TLEN + c * CL) * DI + d;
    const float* al = g_alpha + b * TLEN + c * CL;
    float h = 0.f;
#pragma unroll 8
    for (int tt = 0; tt < CL; tt++) {
        float a = al[tt];
        h = fmaf(a, h, (1.f - a) * xc[(size_t)tt * DI]);
    }
    g_S[((size_t)(b * NC + c)) * DI + d] = h;
}

__global__ __launch_bounds__(256) void scan2_kernel()
{
    const int id = blockIdx.x * 256 + threadIdx.x;
    const int b = id / DI, d = id % DI;
    __shared__ float Ps[NC];
    if (threadIdx.x < NC) {
        const float* al = g_alpha + b * TLEN + threadIdx.x * CL;
        float p = 1.f;
#pragma unroll
        for (int tt = 0; tt < CL; tt++) p *= al[tt];
        Ps[threadIdx.x] = p;
    }
    __syncthreads();
    float h = 0.f;
    g_H0[((size_t)(b * NC + 0)) * DI + d] = 0.f;
#pragma unroll 4
    for (int c = 0; c < NC - 1; c++) {
        h = fmaf(Ps[c], h, g_S[((size_t)(b * NC + c)) * DI + d]);
        g_H0[((size_t)(b * NC + c + 1)) * DI + d] = h;
    }
}

__global__ __launch_bounds__(256) void scan3_kernel(const float* __restrict__ Dp)
{
    const int d = blockIdx.x * 256 + threadIdx.x;
    const int c = blockIdx.y, b = blockIdx.z;
    const size_t rbase = (size_t)b * TLEN + c * CL;
    const float* xc = g_xconv + rbase * DI + d;
    const float* zp = g_xz + rbase * (2 * DI) + DI + d;
    const float* al = g_alpha + b * TLEN + c * CL;
    __nv_bfloat16* yh = g_yh + rbase * DI + d;
    __nv_bfloat16* yl = g_yl + rbase * DI + d;
    const float Dv = Dp[d];
    float h = g_H0[((size_t)(b * NC + c)) * DI + d];
#pragma unroll 4
    for (int tt = 0; tt < CL; tt++) {
        float a = al[tt];
        float x = xc[(size_t)tt * DI];
        h = fmaf(a, h, (1.f - a) * x);
        float y = fmaf(h, Dv, x);
        float z = zp[(size_t)tt * (2 * DI)];
        y = y * siluf_(z);
        __nv_bfloat16 hh = __float2bfloat16_rn(y);
        yh[(size_t)tt * DI] = hh;
        yl[(size_t)tt * DI] = __float2bfloat16_rn(y - __bfloat162float(hh));
    }
}

// ---------------------------------------------------------------------------
extern "C" void kernel_launch(void* const* d_in, const int* in_sizes, int n_in,
                              void* d_out, int out_size)
{
    const float* x    = (const float*)d_in[0];
    const float* win  = (const float*)d_in[1];
    const float* cw   = (const float*)d_in[2];
    const float* cb   = (const float*)d_in[3];
    const float* xpw  = (const float*)d_in[4];
    const float* dtw  = (const float*)d_in[5];
    const float* dtb  = (const float*)d_in[6];
    const float* Dp   = (const float*)d_in[7];
    const float* wout = (const float*)d_in[8];
    float* out = (float*)d_out;

    float* xz; cudaGetSymbolAddress((void**)&xz, g_xz);
    __nv_bfloat16 *xh, *xl, *wih, *wil, *yh, *yl, *woh, *wol;
    cudaGetSymbolAddress((void**)&xh,  g_xh);
    cudaGetSymbolAddress((void**)&xl,  g_xl);
    cudaGetSymbolAddress((void**)&wih, g_wih);
    cudaGetSymbolAddress((void**)&wil, g_wil);
    cudaGetSymbolAddress((void**)&yh,  g_yh);
    cudaGetSymbolAddress((void**)&yl,  g_yl);
    cudaGetSymbolAddress((void**)&woh, g_woh);
    cudaGetSymbolAddress((void**)&wol, g_wol);

    cudaFuncSetAttribute(gemm3_bf, cudaFuncAttributeMaxDynamicSharedMemorySize,
                         GSMEM);

    // 0) all operand conversions in one launch
    cvt_all_kernel<<<(CV_N4 + 255) / 256, 256>>>(x, win, wout, xpw, dtw);
    // 1) in_proj
    gemm3_bf<<<dim3((2 * DI) / 128, MROWS / 128), 256, GSMEM>>>(
        xh, xl, wih, wil, xz, 2 * DI, DM);
    // 2) depthwise causal conv + SiLU
    conv_silu_kernel<<<dim3(DI / 256, TLEN / 32, BSZ), 256>>>(cw, cb);
    // 3) fused B_ssm + dt + alpha (tensor-core)
    proj_alpha_kernel<<<MROWS / 128, 256>>>(dtb);
    // 4) chunked scan
    scan1_kernel<<<dim3(DI / 256, NC, BSZ), 256>>>();
    scan2_kernel<<<MROWS / 256, 256>>>();
    scan3_kernel<<<dim3(DI / 256, NC, BSZ), 256>>>(Dp);
    // 5) out_proj
    gemm3_bf<<<dim3(DM / 128, MROWS / 128), 256, GSMEM>>>(
        yh, yl, woh, wol, out, DM, DI);
}